// round 8
// baseline (speedup 1.0000x reference)
#include <cuda_runtime.h>
#include <cuda_fp16.h>

// MedianBlur 5x5, fp32 I/O, 12 images of 1024x1024, zero padding (same).
// Round-8: occupancy 6 -> 7 CTAs/SM via __launch_bounds__(256,7) (36-reg cap).
// Everything else identical to round 7: wide-LDS packed tile (LDS.64+LDS.128
// per window row), shared row-sort4 + rank-insert band, constrained merges,
// 16-op mid4 merge, 10-op med7 finisher. rel_err must stay bit-identical.

#define IMG_H 1024
#define IMG_W 1024
#define NIMG  12

#define TILE_W 128            // output cols per block (32 threads * 4 px)
#define TILE_H 8              // output rows per block
#define SMEM_H 12             // TILE_H + 4 halo
#define KCOLS 34              // packed cols per group: c = 4*k + g, c in [0,136)

typedef __half2 h2;

__device__ __forceinline__ h2 mn2(h2 a, h2 b) { return __hmin2(a, b); }
__device__ __forceinline__ h2 mx2(h2 a, h2 b) { return __hmax2(a, b); }

__device__ __forceinline__ void ce(h2& a, h2& b) {
    h2 t = mn2(a, b);
    b = mx2(a, b);
    a = t;
}

// 9-CE optimal sorting network for 5 elements (ascending), element-wise on half2.
__device__ __forceinline__ void sort5(h2& v0, h2& v1, h2& v2, h2& v3, h2& v4) {
    ce(v0, v1); ce(v3, v4); ce(v2, v4); ce(v2, v3); ce(v0, v3);
    ce(v0, v2); ce(v1, v4); ce(v1, v3); ce(v1, v2);
}

// Constrained merge of top chains: x0<=x1 (row i ranks {3,4}),
// y0<=y1<=y2 (row i+1 ranks {2,3,4}), with x0<=y1 and x1<=y2. 6 ops.
__device__ __forceinline__ void merge_top(h2 x0, h2 x1, h2 y0, h2 y1, h2 y2,
                                          h2 A[5]) {
    A[0] = mn2(x0, y0);
    h2 p = mx2(x0, y0);
    A[3] = mx2(x1, y1);
    h2 q = mn2(x1, y1);
    A[1] = mn2(p, q);
    A[2] = mx2(p, q);
    A[4] = y2;
}

// Constrained merge of bottom chains: x0<=x1 (row i+1 ranks {0,1}),
// y0<=y1<=y2 (row i ranks {0,1,2}), with y0<=x0 and y1<=x1. 6 ops.
__device__ __forceinline__ void merge_bot(h2 x0, h2 x1, h2 y0, h2 y1, h2 y2,
                                          h2 B[5]) {
    B[0] = y0;
    B[1] = mn2(x0, y1);
    h2 p = mx2(x0, y1);
    h2 q = mn2(x1, y2);
    B[2] = mn2(p, q);
    B[3] = mx2(p, q);
    B[4] = mx2(x1, y2);
}

// Batcher merge of two sorted 5-chains, producing ONLY ranks 3..6 of 10. 16 ops.
__device__ __forceinline__ void merge55_mid4(const h2 A[5], const h2 B[5],
                                             h2& s0, h2& s1, h2& s2, h2& s3) {
    h2 t  = mx2(A[0], B[0]);
    h2 u  = mn2(A[4], B[4]);
    h2 e1 = mn2(t, u);
    h2 e2 = mx2(t, u);
    h2 o0 = mn2(A[2], B[2]);
    h2 o1 = mx2(A[2], B[2]);
    h2 z2 = mx2(o0, e1);
    h2 z3 = mn2(o1, e2);
    h2 tt = mx2(A[1], B[1]);
    h2 uu = mn2(A[3], B[3]);
    h2 w1 = mn2(tt, uu);
    h2 w2 = mx2(tt, uu);
    s0 = mn2(w1, z2); s1 = mx2(w1, z2);
    s2 = mn2(w2, z3); s3 = mx2(w2, z3);
}

// Finisher: med13 == med7({s0<=s1<=s2<=s3} U {m0<=m1<=m2}). 10 ops.
__device__ __forceinline__ h2 med7_fin(h2 s0, h2 s1, h2 s2, h2 s3,
                                       h2 m0, h2 m1, h2 m2) {
    h2 u0 = mx2(s0, m0);
    h2 u3 = mn2(s3, m2);
    h2 p = mn2(u3, m1);
    h2 q = mx2(u3, m1);
    h2 a = mx2(s1, p);
    h2 b = mn2(s2, q);
    h2 lo = mn2(a, b);
    h2 hi = mx2(a, b);
    return mx2(lo, mn2(hi, u0));
}

__global__ __launch_bounds__(256, 7)
void median5x5_h2_kernel(const float* __restrict__ in, float* __restrict__ out) {
    // Packed tile: P2[c] = (h[c], h[c+2]), c = 4k + g, stored p2t[r][k][g]
    // with g contiguous -> 16-byte groups readable by LDS.128 / LDS.64.
    __shared__ __align__(16) h2 p2t[SMEM_H][KCOLS][4];

    const int n   = blockIdx.z;
    const int x0b = blockIdx.x * TILE_W;
    const int y0b = blockIdx.y * TILE_H;
    const float* img = in + (size_t)n * IMG_H * IMG_W;

    const int tx = threadIdx.x;
    const int ty = threadIdx.y;
    const int tid = ty * 32 + tx;

    #pragma unroll
    for (int i = tid; i < SMEM_H * KCOLS; i += 256) {
        const int r  = i / KCOLS;
        const int k  = i - r * KCOLS;
        const int gy  = y0b + r - 2;
        const int gx0 = x0b - 4 + k * 4;
        float f0 = 0.f, f1 = 0.f, f2 = 0.f, f3 = 0.f, f4 = 0.f, f5 = 0.f;
        if ((unsigned)gy < IMG_H) {
            const float* rowp = img + (size_t)gy * IMG_W;
            if (gx0 >= 0 && gx0 + 5 < IMG_W) {
                const float4 fa = *reinterpret_cast<const float4*>(rowp + gx0);
                const float2 fb = *reinterpret_cast<const float2*>(rowp + gx0 + 4);
                f0 = fa.x; f1 = fa.y; f2 = fa.z; f3 = fa.w; f4 = fb.x; f5 = fb.y;
            } else {
                if ((unsigned)gx0       < IMG_W) f0 = rowp[gx0];
                if ((unsigned)(gx0 + 1) < IMG_W) f1 = rowp[gx0 + 1];
                if ((unsigned)(gx0 + 2) < IMG_W) f2 = rowp[gx0 + 2];
                if ((unsigned)(gx0 + 3) < IMG_W) f3 = rowp[gx0 + 3];
                if ((unsigned)(gx0 + 4) < IMG_W) f4 = rowp[gx0 + 4];
                if ((unsigned)(gx0 + 5) < IMG_W) f5 = rowp[gx0 + 5];
            }
        }
        const h2 p0 = __float22half2_rn(make_float2(f0, f2));
        const h2 p1 = __float22half2_rn(make_float2(f1, f3));
        const h2 p2 = __float22half2_rn(make_float2(f2, f4));
        const h2 p3 = __float22half2_rn(make_float2(f3, f5));
        uint4 w;
        w.x = *reinterpret_cast<const unsigned*>(&p0);
        w.y = *reinterpret_cast<const unsigned*>(&p1);
        w.z = *reinterpret_cast<const unsigned*>(&p2);
        w.w = *reinterpret_cast<const unsigned*>(&p3);
        *reinterpret_cast<uint4*>(&p2t[r][k][0]) = w;
    }
    __syncthreads();

    // Thread handles pixels p0..p0+3 (p0 = tx*4) as pairs (p0,p0+2),(p0+1,p0+3).
    // Packed col m (m=0..5) is P2[4tx+2+m]:
    //   m=0,1 -> p2t[row][tx][2..3]   (one LDS.64)
    //   m=2..5 -> p2t[row][tx+1][0..3] (one LDS.128)
    h2 col[6][5];
    #pragma unroll
    for (int i = 0; i < 5; i++) {
        const uint2 lo = *reinterpret_cast<const uint2*>(&p2t[ty + i][tx][2]);
        const uint4 hi = *reinterpret_cast<const uint4*>(&p2t[ty + i][tx + 1][0]);
        col[0][i] = *reinterpret_cast<const h2*>(&lo.x);
        col[1][i] = *reinterpret_cast<const h2*>(&lo.y);
        col[2][i] = *reinterpret_cast<const h2*>(&hi.x);
        col[3][i] = *reinterpret_cast<const h2*>(&hi.y);
        col[4][i] = *reinterpret_cast<const h2*>(&hi.z);
        col[5][i] = *reinterpret_cast<const h2*>(&hi.w);
    }

    #pragma unroll
    for (int m = 0; m < 6; m++)
        sort5(col[m][0], col[m][1], col[m][2], col[m][3], col[m][4]);

    // ---- Row phase: partial shared sorts of cols 1..4, rank-insert c0 / c5 ----
    h2 a03, a04, a12, a13, a14, aM1, aM2, aM3, a30, a31, a32, a40, a41;
    h2 b03, b04, b12, b13, b14, bM1, bM2, bM3, b30, b31, b32, b40, b41;

    {   // row 0: top2 of 4, insert -> ranks {3,4}
        h2 a = mn2(col[1][0], col[2][0]), b = mx2(col[1][0], col[2][0]);
        h2 c = mn2(col[3][0], col[4][0]), d = mx2(col[3][0], col[4][0]);
        h2 q3 = mx2(b, d);
        h2 q2 = mx2(mn2(b, d), mx2(a, c));
        h2 xa = col[0][0], xb = col[5][0];
        a04 = mx2(q3, xa); a03 = mx2(q2, mn2(q3, xa));
        b04 = mx2(q3, xb); b03 = mx2(q2, mn2(q3, xb));
    }
    {   // row 1: sort4 minus q0, insert -> ranks {2,3,4}
        h2 v0 = col[1][1], v1 = col[2][1], v2 = col[3][1], v3 = col[4][1];
        ce(v0, v1); ce(v2, v3);
        v2 = mx2(v0, v2);
        ce(v1, v3); ce(v1, v2);
        const h2 q1 = v1, q2 = v2, q3 = v3;
        h2 xa = col[0][1], xb = col[5][1];
        a14 = mx2(q3, xa); a13 = mx2(q2, mn2(q3, xa)); a12 = mx2(q1, mn2(q2, xa));
        b14 = mx2(q3, xb); b13 = mx2(q2, mn2(q3, xb)); b12 = mx2(q1, mn2(q2, xb));
    }
    {   // row 2: full sort4, insert -> mid3 ranks {1,2,3}
        h2 q0 = col[1][2], q1 = col[2][2], q2 = col[3][2], q3 = col[4][2];
        ce(q0, q1); ce(q2, q3); ce(q0, q2); ce(q1, q3); ce(q1, q2);
        h2 xa = col[0][2], xb = col[5][2];
        aM3 = mx2(q2, mn2(q3, xa)); aM2 = mx2(q1, mn2(q2, xa)); aM1 = mx2(q0, mn2(q1, xa));
        bM3 = mx2(q2, mn2(q3, xb)); bM2 = mx2(q1, mn2(q2, xb)); bM1 = mx2(q0, mn2(q1, xb));
    }
    {   // row 3: sort4 minus q3, insert -> ranks {0,1,2}
        h2 v0 = col[1][3], v1 = col[2][3], v2 = col[3][3], v3 = col[4][3];
        ce(v0, v1); ce(v2, v3); ce(v0, v2);
        v1 = mn2(v1, v3);
        ce(v1, v2);
        const h2 q0 = v0, q1 = v1, q2 = v2;
        h2 xa = col[0][3], xb = col[5][3];
        a30 = mn2(q0, xa); a31 = mx2(q0, mn2(q1, xa)); a32 = mx2(q1, mn2(q2, xa));
        b30 = mn2(q0, xb); b31 = mx2(q0, mn2(q1, xb)); b32 = mx2(q1, mn2(q2, xb));
    }
    {   // row 4: bottom2 of 4, insert -> ranks {0,1}
        h2 a = mn2(col[1][4], col[2][4]), b = mx2(col[1][4], col[2][4]);
        h2 c = mn2(col[3][4], col[4][4]), d = mx2(col[3][4], col[4][4]);
        h2 q0 = mn2(a, c);
        h2 q1 = mn2(mx2(a, c), mn2(b, d));
        h2 xa = col[0][4], xb = col[5][4];
        a40 = mn2(q0, xa); a41 = mx2(q0, mn2(q1, xa));
        b40 = mn2(q0, xb); b41 = mx2(q0, mn2(q1, xb));
    }

    // ---- Merge phase per network (constrained merges) ----
    h2 rA, rB;
    {
        h2 A[5], B[5];
        merge_top(a03, a04, a12, a13, a14, A);
        merge_bot(a40, a41, a30, a31, a32, B);
        h2 s0, s1, s2, s3;
        merge55_mid4(A, B, s0, s1, s2, s3);
        rA = med7_fin(s0, s1, s2, s3, aM1, aM2, aM3);
    }
    {
        h2 A[5], B[5];
        merge_top(b03, b04, b12, b13, b14, A);
        merge_bot(b40, b41, b30, b31, b32, B);
        h2 s0, s1, s2, s3;
        merge55_mid4(A, B, s0, s1, s2, s3);
        rB = med7_fin(s0, s1, s2, s3, bM1, bM2, bM3);
    }

    float4 res;
    res.x = __low2float(rA);    // pixel p0
    res.y = __low2float(rB);    // pixel p0+1
    res.z = __high2float(rA);   // pixel p0+2
    res.w = __high2float(rB);   // pixel p0+3

    float* orow = out + (size_t)n * IMG_H * IMG_W
                      + (size_t)(y0b + ty) * IMG_W + x0b + tx * 4;
    *reinterpret_cast<float4*>(orow) = res;
}

extern "C" void kernel_launch(void* const* d_in, const int* in_sizes, int n_in,
                              void* d_out, int out_size) {
    (void)in_sizes; (void)n_in; (void)out_size;
    const float* in = (const float*)d_in[0];
    float* out = (float*)d_out;

    dim3 block(32, TILE_H, 1);
    dim3 grid(IMG_W / TILE_W, IMG_H / TILE_H, NIMG);
    median5x5_h2_kernel<<<grid, block>>>(in, out);
}

// round 9
// speedup vs baseline: 1.0364x; 1.0364x over previous
#include <cuda_runtime.h>
#include <cuda_fp16.h>

// MedianBlur 5x5, fp32 I/O, 12 images of 1024x1024, zero padding (same).
// Round-9: candidate pruning 13 -> 11. A0 = min(r0[3],r1[2]) has >=7 of the
// other 12 candidates >= it (rank <= 5); B4 = max(r4[1],r3[2]) dually rank
// >= 7. Balanced removal -> med13 = med11{A1..A4, B0..B3, M0..M2}.
// Batcher 4x4 merge keeping ranks 2..5 (14 ops) + med7 finisher (10 ops).
// merge_top/merge_bot 6 -> 5 ops. Everything else = round 7 (wide-LDS packed
// tile, shared row-sort4 + rank-insert band). launch_bounds(256,6).

#define IMG_H 1024
#define IMG_W 1024
#define NIMG  12

#define TILE_W 128            // output cols per block (32 threads * 4 px)
#define TILE_H 8              // output rows per block
#define SMEM_H 12             // TILE_H + 4 halo
#define KCOLS 34              // packed cols per group: c = 4*k + g, c in [0,136)

typedef __half2 h2;

__device__ __forceinline__ h2 mn2(h2 a, h2 b) { return __hmin2(a, b); }
__device__ __forceinline__ h2 mx2(h2 a, h2 b) { return __hmax2(a, b); }

__device__ __forceinline__ void ce(h2& a, h2& b) {
    h2 t = mn2(a, b);
    b = mx2(a, b);
    a = t;
}

// 9-CE optimal sorting network for 5 elements (ascending), element-wise on half2.
__device__ __forceinline__ void sort5(h2& v0, h2& v1, h2& v2, h2& v3, h2& v4) {
    ce(v0, v1); ce(v3, v4); ce(v2, v4); ce(v2, v3); ce(v0, v3);
    ce(v0, v2); ce(v1, v4); ce(v1, v3); ce(v1, v2);
}

// Constrained merge of top chains, DROPPING rank 0 (provably non-median).
// x0<=x1 (row i ranks {3,4}), y0<=y1<=y2 (row i+1 ranks {2,3,4}),
// with x0<=y1, x1<=y2 (column order). Outputs ranks 1..4. 5 ops.
__device__ __forceinline__ void merge_top4(h2 x0, h2 x1, h2 y0, h2 y1, h2 y2,
                                           h2& a1, h2& a2, h2& a3, h2& a4) {
    h2 p = mx2(x0, y0);
    h2 q = mn2(x1, y1);
    a3 = mx2(x1, y1);
    a1 = mn2(p, q);
    a2 = mx2(p, q);
    a4 = y2;
}

// Constrained merge of bottom chains, DROPPING rank 4 (provably non-median).
// x0<=x1 (row i+1 ranks {0,1}), y0<=y1<=y2 (row i ranks {0,1,2}),
// with y0<=x0, y1<=x1. Outputs ranks 0..3. 5 ops.
__device__ __forceinline__ void merge_bot4(h2 x0, h2 x1, h2 y0, h2 y1, h2 y2,
                                           h2& b0, h2& b1, h2& b2, h2& b3) {
    b0 = y0;
    b1 = mn2(x0, y1);
    h2 p = mx2(x0, y1);
    h2 q = mn2(x1, y2);
    b2 = mn2(p, q);
    b3 = mx2(p, q);
}

// Batcher odd-even merge of two sorted 4-chains (a1..a4, b0..b3), producing
// ONLY ranks 2..5 of the 8. 14 ops.
__device__ __forceinline__ void merge44_mid4(h2 a1, h2 a2, h2 a3, h2 a4,
                                             h2 b0, h2 b1, h2 b2, h2 b3,
                                             h2& s0, h2& s1, h2& s2, h2& s3) {
    // evens: (a1,a3) x (b0,b2) -> E1,E2,E3 (E0 dead)
    h2 t  = mx2(a1, b0);
    h2 u  = mn2(a3, b2);
    h2 E3 = mx2(a3, b2);
    h2 E1 = mn2(t, u);
    h2 E2 = mx2(t, u);
    // odds: (a2,a4) x (b1,b3) -> O0,O1,O2 (O3 dead)
    h2 O0 = mn2(a2, b1);
    h2 t2 = mx2(a2, b1);
    h2 u2 = mn2(a4, b3);
    h2 O1 = mn2(t2, u2);
    h2 O2 = mx2(t2, u2);
    // z2..z5 = mx(O0,E1), mn(O1,E2), mx(O1,E2), mn(O2,E3)
    s0 = mx2(O0, E1);
    s1 = mn2(O1, E2);
    s2 = mx2(O1, E2);
    s3 = mn2(O2, E3);
}

// Finisher: med11 == med7({s0<=s1<=s2<=s3} U {m0<=m1<=m2}). 10 ops.
__device__ __forceinline__ h2 med7_fin(h2 s0, h2 s1, h2 s2, h2 s3,
                                       h2 m0, h2 m1, h2 m2) {
    h2 u0 = mx2(s0, m0);
    h2 u3 = mn2(s3, m2);
    h2 p = mn2(u3, m1);
    h2 q = mx2(u3, m1);
    h2 a = mx2(s1, p);
    h2 b = mn2(s2, q);
    h2 lo = mn2(a, b);
    h2 hi = mx2(a, b);
    return mx2(lo, mn2(hi, u0));
}

__global__ __launch_bounds__(256, 6)
void median5x5_h2_kernel(const float* __restrict__ in, float* __restrict__ out) {
    // Packed tile: P2[c] = (h[c], h[c+2]), c = 4k + g, stored p2t[r][k][g]
    // with g contiguous -> 16-byte groups readable by LDS.128 / LDS.64.
    __shared__ __align__(16) h2 p2t[SMEM_H][KCOLS][4];

    const int n   = blockIdx.z;
    const int x0b = blockIdx.x * TILE_W;
    const int y0b = blockIdx.y * TILE_H;
    const float* img = in + (size_t)n * IMG_H * IMG_W;

    const int tx = threadIdx.x;
    const int ty = threadIdx.y;
    const int tid = ty * 32 + tx;

    #pragma unroll
    for (int i = tid; i < SMEM_H * KCOLS; i += 256) {
        const int r  = i / KCOLS;
        const int k  = i - r * KCOLS;
        const int gy  = y0b + r - 2;
        const int gx0 = x0b - 4 + k * 4;
        float f0 = 0.f, f1 = 0.f, f2 = 0.f, f3 = 0.f, f4 = 0.f, f5 = 0.f;
        if ((unsigned)gy < IMG_H) {
            const float* rowp = img + (size_t)gy * IMG_W;
            if (gx0 >= 0 && gx0 + 5 < IMG_W) {
                const float4 fa = *reinterpret_cast<const float4*>(rowp + gx0);
                const float2 fb = *reinterpret_cast<const float2*>(rowp + gx0 + 4);
                f0 = fa.x; f1 = fa.y; f2 = fa.z; f3 = fa.w; f4 = fb.x; f5 = fb.y;
            } else {
                if ((unsigned)gx0       < IMG_W) f0 = rowp[gx0];
                if ((unsigned)(gx0 + 1) < IMG_W) f1 = rowp[gx0 + 1];
                if ((unsigned)(gx0 + 2) < IMG_W) f2 = rowp[gx0 + 2];
                if ((unsigned)(gx0 + 3) < IMG_W) f3 = rowp[gx0 + 3];
                if ((unsigned)(gx0 + 4) < IMG_W) f4 = rowp[gx0 + 4];
                if ((unsigned)(gx0 + 5) < IMG_W) f5 = rowp[gx0 + 5];
            }
        }
        const h2 p0 = __float22half2_rn(make_float2(f0, f2));
        const h2 p1 = __float22half2_rn(make_float2(f1, f3));
        const h2 p2 = __float22half2_rn(make_float2(f2, f4));
        const h2 p3 = __float22half2_rn(make_float2(f3, f5));
        uint4 w;
        w.x = *reinterpret_cast<const unsigned*>(&p0);
        w.y = *reinterpret_cast<const unsigned*>(&p1);
        w.z = *reinterpret_cast<const unsigned*>(&p2);
        w.w = *reinterpret_cast<const unsigned*>(&p3);
        *reinterpret_cast<uint4*>(&p2t[r][k][0]) = w;
    }
    __syncthreads();

    // Thread handles pixels p0..p0+3 (p0 = tx*4) as pairs (p0,p0+2),(p0+1,p0+3).
    // Packed col m (m=0..5) is P2[4tx+2+m]:
    //   m=0,1 -> p2t[row][tx][2..3]   (one LDS.64)
    //   m=2..5 -> p2t[row][tx+1][0..3] (one LDS.128)
    h2 col[6][5];
    #pragma unroll
    for (int i = 0; i < 5; i++) {
        const uint2 lo = *reinterpret_cast<const uint2*>(&p2t[ty + i][tx][2]);
        const uint4 hi = *reinterpret_cast<const uint4*>(&p2t[ty + i][tx + 1][0]);
        col[0][i] = *reinterpret_cast<const h2*>(&lo.x);
        col[1][i] = *reinterpret_cast<const h2*>(&lo.y);
        col[2][i] = *reinterpret_cast<const h2*>(&hi.x);
        col[3][i] = *reinterpret_cast<const h2*>(&hi.y);
        col[4][i] = *reinterpret_cast<const h2*>(&hi.z);
        col[5][i] = *reinterpret_cast<const h2*>(&hi.w);
    }

    #pragma unroll
    for (int m = 0; m < 6; m++)
        sort5(col[m][0], col[m][1], col[m][2], col[m][3], col[m][4]);

    // ---- Row phase: partial shared sorts of cols 1..4, rank-insert c0 / c5 ----
    h2 a03, a04, a12, a13, a14, aM1, aM2, aM3, a30, a31, a32, a40, a41;
    h2 b03, b04, b12, b13, b14, bM1, bM2, bM3, b30, b31, b32, b40, b41;

    {   // row 0: top2 of 4, insert -> ranks {3,4}
        h2 a = mn2(col[1][0], col[2][0]), b = mx2(col[1][0], col[2][0]);
        h2 c = mn2(col[3][0], col[4][0]), d = mx2(col[3][0], col[4][0]);
        h2 q3 = mx2(b, d);
        h2 q2 = mx2(mn2(b, d), mx2(a, c));
        h2 xa = col[0][0], xb = col[5][0];
        a04 = mx2(q3, xa); a03 = mx2(q2, mn2(q3, xa));
        b04 = mx2(q3, xb); b03 = mx2(q2, mn2(q3, xb));
    }
    {   // row 1: sort4 minus q0, insert -> ranks {2,3,4}
        h2 v0 = col[1][1], v1 = col[2][1], v2 = col[3][1], v3 = col[4][1];
        ce(v0, v1); ce(v2, v3);
        v2 = mx2(v0, v2);
        ce(v1, v3); ce(v1, v2);
        const h2 q1 = v1, q2 = v2, q3 = v3;
        h2 xa = col[0][1], xb = col[5][1];
        a14 = mx2(q3, xa); a13 = mx2(q2, mn2(q3, xa)); a12 = mx2(q1, mn2(q2, xa));
        b14 = mx2(q3, xb); b13 = mx2(q2, mn2(q3, xb)); b12 = mx2(q1, mn2(q2, xb));
    }
    {   // row 2: full sort4, insert -> mid3 ranks {1,2,3}
        h2 q0 = col[1][2], q1 = col[2][2], q2 = col[3][2], q3 = col[4][2];
        ce(q0, q1); ce(q2, q3); ce(q0, q2); ce(q1, q3); ce(q1, q2);
        h2 xa = col[0][2], xb = col[5][2];
        aM3 = mx2(q2, mn2(q3, xa)); aM2 = mx2(q1, mn2(q2, xa)); aM1 = mx2(q0, mn2(q1, xa));
        bM3 = mx2(q2, mn2(q3, xb)); bM2 = mx2(q1, mn2(q2, xb)); bM1 = mx2(q0, mn2(q1, xb));
    }
    {   // row 3: sort4 minus q3, insert -> ranks {0,1,2}
        h2 v0 = col[1][3], v1 = col[2][3], v2 = col[3][3], v3 = col[4][3];
        ce(v0, v1); ce(v2, v3); ce(v0, v2);
        v1 = mn2(v1, v3);
        ce(v1, v2);
        const h2 q0 = v0, q1 = v1, q2 = v2;
        h2 xa = col[0][3], xb = col[5][3];
        a30 = mn2(q0, xa); a31 = mx2(q0, mn2(q1, xa)); a32 = mx2(q1, mn2(q2, xa));
        b30 = mn2(q0, xb); b31 = mx2(q0, mn2(q1, xb)); b32 = mx2(q1, mn2(q2, xb));
    }
    {   // row 4: bottom2 of 4, insert -> ranks {0,1}
        h2 a = mn2(col[1][4], col[2][4]), b = mx2(col[1][4], col[2][4]);
        h2 c = mn2(col[3][4], col[4][4]), d = mx2(col[3][4], col[4][4]);
        h2 q0 = mn2(a, c);
        h2 q1 = mn2(mx2(a, c), mn2(b, d));
        h2 xa = col[0][4], xb = col[5][4];
        a40 = mn2(q0, xa); a41 = mx2(q0, mn2(q1, xa));
        b40 = mn2(q0, xb); b41 = mx2(q0, mn2(q1, xb));
    }

    // ---- Merge phase per network (pruned 11-candidate selection) ----
    h2 rA, rB;
    {
        h2 a1, a2, a3, a4, c0, c1, c2, c3;
        merge_top4(a03, a04, a12, a13, a14, a1, a2, a3, a4);
        merge_bot4(a40, a41, a30, a31, a32, c0, c1, c2, c3);
        h2 s0, s1, s2, s3;
        merge44_mid4(a1, a2, a3, a4, c0, c1, c2, c3, s0, s1, s2, s3);
        rA = med7_fin(s0, s1, s2, s3, aM1, aM2, aM3);
    }
    {
        h2 a1, a2, a3, a4, c0, c1, c2, c3;
        merge_top4(b03, b04, b12, b13, b14, a1, a2, a3, a4);
        merge_bot4(b40, b41, b30, b31, b32, c0, c1, c2, c3);
        h2 s0, s1, s2, s3;
        merge44_mid4(a1, a2, a3, a4, c0, c1, c2, c3, s0, s1, s2, s3);
        rB = med7_fin(s0, s1, s2, s3, bM1, bM2, bM3);
    }

    float4 res;
    res.x = __low2float(rA);    // pixel p0
    res.y = __low2float(rB);    // pixel p0+1
    res.z = __high2float(rA);   // pixel p0+2
    res.w = __high2float(rB);   // pixel p0+3

    float* orow = out + (size_t)n * IMG_H * IMG_W
                      + (size_t)(y0b + ty) * IMG_W + x0b + tx * 4;
    *reinterpret_cast<float4*>(orow) = res;
}

extern "C" void kernel_launch(void* const* d_in, const int* in_sizes, int n_in,
                              void* d_out, int out_size) {
    (void)in_sizes; (void)n_in; (void)out_size;
    const float* in = (const float*)d_in[0];
    float* out = (float*)d_out;

    dim3 block(32, TILE_H, 1);
    dim3 grid(IMG_W / TILE_W, IMG_H / TILE_H, NIMG);
    median5x5_h2_kernel<<<grid, block>>>(in, out);
}

// round 10
// speedup vs baseline: 1.0761x; 1.0383x over previous
#include <cuda_runtime.h>
#include <cuda_fp16.h>

// MedianBlur 5x5, fp32 I/O, 12 images of 1024x1024, zero padding (same).
// Round-10: tall tiles. Each block outputs 24 rows (3 row-groups of 8);
// each thread computes 3 output rows sequentially, reusing col[6][5] regs.
// Halo overhead 1.5x -> 1.17x, waves 14 -> ~4.7, one loader+barrier per
// 3x compute. Network identical to round 9 (11-candidate pruned selection)
// -> rel_err bit-identical.

#define IMG_H 1024
#define IMG_W 1024
#define NIMG  12

#define TILE_W 128            // output cols per block (32 threads * 4 px)
#define OUT_H  24             // output rows per block (3 groups of 8)
#define SMEM_H 28             // OUT_H + 4 halo
#define KCOLS 34              // packed cols per group: c = 4*k + g, c in [0,136)

typedef __half2 h2;

__device__ __forceinline__ h2 mn2(h2 a, h2 b) { return __hmin2(a, b); }
__device__ __forceinline__ h2 mx2(h2 a, h2 b) { return __hmax2(a, b); }

__device__ __forceinline__ void ce(h2& a, h2& b) {
    h2 t = mn2(a, b);
    b = mx2(a, b);
    a = t;
}

// 9-CE optimal sorting network for 5 elements (ascending), element-wise on half2.
__device__ __forceinline__ void sort5(h2& v0, h2& v1, h2& v2, h2& v3, h2& v4) {
    ce(v0, v1); ce(v3, v4); ce(v2, v4); ce(v2, v3); ce(v0, v3);
    ce(v0, v2); ce(v1, v4); ce(v1, v3); ce(v1, v2);
}

// Constrained merge of top chains, DROPPING rank 0 (provably non-median). 5 ops.
__device__ __forceinline__ void merge_top4(h2 x0, h2 x1, h2 y0, h2 y1, h2 y2,
                                           h2& a1, h2& a2, h2& a3, h2& a4) {
    h2 p = mx2(x0, y0);
    h2 q = mn2(x1, y1);
    a3 = mx2(x1, y1);
    a1 = mn2(p, q);
    a2 = mx2(p, q);
    a4 = y2;
}

// Constrained merge of bottom chains, DROPPING rank 4 (provably non-median). 5 ops.
__device__ __forceinline__ void merge_bot4(h2 x0, h2 x1, h2 y0, h2 y1, h2 y2,
                                           h2& b0, h2& b1, h2& b2, h2& b3) {
    b0 = y0;
    b1 = mn2(x0, y1);
    h2 p = mx2(x0, y1);
    h2 q = mn2(x1, y2);
    b2 = mn2(p, q);
    b3 = mx2(p, q);
}

// Batcher odd-even merge of two sorted 4-chains, ONLY ranks 2..5 of 8. 14 ops.
__device__ __forceinline__ void merge44_mid4(h2 a1, h2 a2, h2 a3, h2 a4,
                                             h2 b0, h2 b1, h2 b2, h2 b3,
                                             h2& s0, h2& s1, h2& s2, h2& s3) {
    h2 t  = mx2(a1, b0);
    h2 u  = mn2(a3, b2);
    h2 E3 = mx2(a3, b2);
    h2 E1 = mn2(t, u);
    h2 E2 = mx2(t, u);
    h2 O0 = mn2(a2, b1);
    h2 t2 = mx2(a2, b1);
    h2 u2 = mn2(a4, b3);
    h2 O1 = mn2(t2, u2);
    h2 O2 = mx2(t2, u2);
    s0 = mx2(O0, E1);
    s1 = mn2(O1, E2);
    s2 = mx2(O1, E2);
    s3 = mn2(O2, E3);
}

// Finisher: med11 == med7({s0<=s1<=s2<=s3} U {m0<=m1<=m2}). 10 ops.
__device__ __forceinline__ h2 med7_fin(h2 s0, h2 s1, h2 s2, h2 s3,
                                       h2 m0, h2 m1, h2 m2) {
    h2 u0 = mx2(s0, m0);
    h2 u3 = mn2(s3, m2);
    h2 p = mn2(u3, m1);
    h2 q = mx2(u3, m1);
    h2 a = mx2(s1, p);
    h2 b = mn2(s2, q);
    h2 lo = mn2(a, b);
    h2 hi = mx2(a, b);
    return mx2(lo, mn2(hi, u0));
}

__global__ __launch_bounds__(256, 6)
void median5x5_h2_kernel(const float* __restrict__ in, float* __restrict__ out) {
    // Packed tile: P2[c] = (h[c], h[c+2]), c = 4k + g, stored p2t[r][k][g]
    // with g contiguous -> 16-byte groups readable by LDS.128 / LDS.64.
    __shared__ __align__(16) h2 p2t[SMEM_H][KCOLS][4];

    const int n   = blockIdx.z;
    const int x0b = blockIdx.x * TILE_W;
    const int y0b = blockIdx.y * OUT_H;
    const float* img = in + (size_t)n * IMG_H * IMG_W;

    const int tx = threadIdx.x;
    const int ty = threadIdx.y;
    const int tid = ty * 32 + tx;

    // Loader: 28 x 34 packed-column tasks, zero padding on all edges.
    for (int i = tid; i < SMEM_H * KCOLS; i += 256) {
        const int r  = i / KCOLS;
        const int k  = i - r * KCOLS;
        const int gy  = y0b + r - 2;
        const int gx0 = x0b - 4 + k * 4;
        float f0 = 0.f, f1 = 0.f, f2 = 0.f, f3 = 0.f, f4 = 0.f, f5 = 0.f;
        if ((unsigned)gy < IMG_H) {
            const float* rowp = img + (size_t)gy * IMG_W;
            if (gx0 >= 0 && gx0 + 5 < IMG_W) {
                const float4 fa = *reinterpret_cast<const float4*>(rowp + gx0);
                const float2 fb = *reinterpret_cast<const float2*>(rowp + gx0 + 4);
                f0 = fa.x; f1 = fa.y; f2 = fa.z; f3 = fa.w; f4 = fb.x; f5 = fb.y;
            } else {
                if ((unsigned)gx0       < IMG_W) f0 = rowp[gx0];
                if ((unsigned)(gx0 + 1) < IMG_W) f1 = rowp[gx0 + 1];
                if ((unsigned)(gx0 + 2) < IMG_W) f2 = rowp[gx0 + 2];
                if ((unsigned)(gx0 + 3) < IMG_W) f3 = rowp[gx0 + 3];
                if ((unsigned)(gx0 + 4) < IMG_W) f4 = rowp[gx0 + 4];
                if ((unsigned)(gx0 + 5) < IMG_W) f5 = rowp[gx0 + 5];
            }
        }
        const h2 p0 = __float22half2_rn(make_float2(f0, f2));
        const h2 p1 = __float22half2_rn(make_float2(f1, f3));
        const h2 p2 = __float22half2_rn(make_float2(f2, f4));
        const h2 p3 = __float22half2_rn(make_float2(f3, f5));
        uint4 w;
        w.x = *reinterpret_cast<const unsigned*>(&p0);
        w.y = *reinterpret_cast<const unsigned*>(&p1);
        w.z = *reinterpret_cast<const unsigned*>(&p2);
        w.w = *reinterpret_cast<const unsigned*>(&p3);
        *reinterpret_cast<uint4*>(&p2t[r][k][0]) = w;
    }
    __syncthreads();

    // Three output row-groups per thread; col[6][5] registers reused.
    #pragma unroll 1
    for (int gr = 0; gr < 3; gr++) {
        const int rb = ty + gr * 8;          // smem base row of the window
        const int y  = y0b + rb;             // global output row
        if (y >= IMG_H) break;

        // Packed col m (m=0..5) is P2[4tx+2+m]:
        //   m=0,1 -> p2t[row][tx][2..3]   (one LDS.64)
        //   m=2..5 -> p2t[row][tx+1][0..3] (one LDS.128)
        h2 col[6][5];
        #pragma unroll
        for (int i = 0; i < 5; i++) {
            const uint2 lo = *reinterpret_cast<const uint2*>(&p2t[rb + i][tx][2]);
            const uint4 hi = *reinterpret_cast<const uint4*>(&p2t[rb + i][tx + 1][0]);
            col[0][i] = *reinterpret_cast<const h2*>(&lo.x);
            col[1][i] = *reinterpret_cast<const h2*>(&lo.y);
            col[2][i] = *reinterpret_cast<const h2*>(&hi.x);
            col[3][i] = *reinterpret_cast<const h2*>(&hi.y);
            col[4][i] = *reinterpret_cast<const h2*>(&hi.z);
            col[5][i] = *reinterpret_cast<const h2*>(&hi.w);
        }

        #pragma unroll
        for (int m = 0; m < 6; m++)
            sort5(col[m][0], col[m][1], col[m][2], col[m][3], col[m][4]);

        // ---- Row phase: partial shared sorts of cols 1..4, rank-insert c0/c5 ----
        h2 a03, a04, a12, a13, a14, aM1, aM2, aM3, a30, a31, a32, a40, a41;
        h2 b03, b04, b12, b13, b14, bM1, bM2, bM3, b30, b31, b32, b40, b41;

        {   // row 0: top2 of 4, insert -> ranks {3,4}
            h2 a = mn2(col[1][0], col[2][0]), b = mx2(col[1][0], col[2][0]);
            h2 c = mn2(col[3][0], col[4][0]), d = mx2(col[3][0], col[4][0]);
            h2 q3 = mx2(b, d);
            h2 q2 = mx2(mn2(b, d), mx2(a, c));
            h2 xa = col[0][0], xb = col[5][0];
            a04 = mx2(q3, xa); a03 = mx2(q2, mn2(q3, xa));
            b04 = mx2(q3, xb); b03 = mx2(q2, mn2(q3, xb));
        }
        {   // row 1: sort4 minus q0, insert -> ranks {2,3,4}
            h2 v0 = col[1][1], v1 = col[2][1], v2 = col[3][1], v3 = col[4][1];
            ce(v0, v1); ce(v2, v3);
            v2 = mx2(v0, v2);
            ce(v1, v3); ce(v1, v2);
            const h2 q1 = v1, q2 = v2, q3 = v3;
            h2 xa = col[0][1], xb = col[5][1];
            a14 = mx2(q3, xa); a13 = mx2(q2, mn2(q3, xa)); a12 = mx2(q1, mn2(q2, xa));
            b14 = mx2(q3, xb); b13 = mx2(q2, mn2(q3, xb)); b12 = mx2(q1, mn2(q2, xb));
        }
        {   // row 2: full sort4, insert -> mid3 ranks {1,2,3}
            h2 q0 = col[1][2], q1 = col[2][2], q2 = col[3][2], q3 = col[4][2];
            ce(q0, q1); ce(q2, q3); ce(q0, q2); ce(q1, q3); ce(q1, q2);
            h2 xa = col[0][2], xb = col[5][2];
            aM3 = mx2(q2, mn2(q3, xa)); aM2 = mx2(q1, mn2(q2, xa)); aM1 = mx2(q0, mn2(q1, xa));
            bM3 = mx2(q2, mn2(q3, xb)); bM2 = mx2(q1, mn2(q2, xb)); bM1 = mx2(q0, mn2(q1, xb));
        }
        {   // row 3: sort4 minus q3, insert -> ranks {0,1,2}
            h2 v0 = col[1][3], v1 = col[2][3], v2 = col[3][3], v3 = col[4][3];
            ce(v0, v1); ce(v2, v3); ce(v0, v2);
            v1 = mn2(v1, v3);
            ce(v1, v2);
            const h2 q0 = v0, q1 = v1, q2 = v2;
            h2 xa = col[0][3], xb = col[5][3];
            a30 = mn2(q0, xa); a31 = mx2(q0, mn2(q1, xa)); a32 = mx2(q1, mn2(q2, xa));
            b30 = mn2(q0, xb); b31 = mx2(q0, mn2(q1, xb)); b32 = mx2(q1, mn2(q2, xb));
        }
        {   // row 4: bottom2 of 4, insert -> ranks {0,1}
            h2 a = mn2(col[1][4], col[2][4]), b = mx2(col[1][4], col[2][4]);
            h2 c = mn2(col[3][4], col[4][4]), d = mx2(col[3][4], col[4][4]);
            h2 q0 = mn2(a, c);
            h2 q1 = mn2(mx2(a, c), mn2(b, d));
            h2 xa = col[0][4], xb = col[5][4];
            a40 = mn2(q0, xa); a41 = mx2(q0, mn2(q1, xa));
            b40 = mn2(q0, xb); b41 = mx2(q0, mn2(q1, xb));
        }

        // ---- Merge phase per network (pruned 11-candidate selection) ----
        h2 rA, rB;
        {
            h2 a1, a2, a3, a4, c0, c1, c2, c3;
            merge_top4(a03, a04, a12, a13, a14, a1, a2, a3, a4);
            merge_bot4(a40, a41, a30, a31, a32, c0, c1, c2, c3);
            h2 s0, s1, s2, s3;
            merge44_mid4(a1, a2, a3, a4, c0, c1, c2, c3, s0, s1, s2, s3);
            rA = med7_fin(s0, s1, s2, s3, aM1, aM2, aM3);
        }
        {
            h2 a1, a2, a3, a4, c0, c1, c2, c3;
            merge_top4(b03, b04, b12, b13, b14, a1, a2, a3, a4);
            merge_bot4(b40, b41, b30, b31, b32, c0, c1, c2, c3);
            h2 s0, s1, s2, s3;
            merge44_mid4(a1, a2, a3, a4, c0, c1, c2, c3, s0, s1, s2, s3);
            rB = med7_fin(s0, s1, s2, s3, bM1, bM2, bM3);
        }

        float4 res;
        res.x = __low2float(rA);    // pixel p0
        res.y = __low2float(rB);    // pixel p0+1
        res.z = __high2float(rA);   // pixel p0+2
        res.w = __high2float(rB);   // pixel p0+3

        float* orow = out + (size_t)n * IMG_H * IMG_W
                          + (size_t)y * IMG_W + x0b + tx * 4;
        *reinterpret_cast<float4*>(orow) = res;
    }
}

extern "C" void kernel_launch(void* const* d_in, const int* in_sizes, int n_in,
                              void* d_out, int out_size) {
    (void)in_sizes; (void)n_in; (void)out_size;
    const float* in = (const float*)d_in[0];
    float* out = (float*)d_out;

    dim3 block(32, 8, 1);
    dim3 grid(IMG_W / TILE_W, (IMG_H + OUT_H - 1) / OUT_H, NIMG);
    median5x5_h2_kernel<<<grid, block>>>(in, out);
}